// round 2
// baseline (speedup 1.0000x reference)
#include <cuda_runtime.h>
#include <cuda_bf16.h>
#include <cstdint>

// Problem constants: N=100000 nodes, D=128, E=1600000 edges.
#define MAX_N 100000
#define DD 128
#define BN_EPS 1e-5f

// Scratch (static __device__ — no allocations allowed)
__device__ __align__(16) float g_agg[MAX_N * DD];   // scatter-sum accumulator
__device__ __align__(16) float g_deg[MAX_N];        // degree -> inverse degree
__device__ __align__(16) float g_colsum[DD];
__device__ __align__(16) float g_colsumsq[DD];
__device__ __align__(16) float g_scale[DD];
__device__ __align__(16) float g_shift[DD];
__device__ int g_idx64;                             // 1 if edge_index is int64

// ---------------------------------------------------------------------------
__global__ void zero_kernel(float* __restrict__ p, int n4) {
    int i = blockIdx.x * blockDim.x + threadIdx.x;
    if (i < n4) reinterpret_cast<float4*>(p)[i] = make_float4(0.f, 0.f, 0.f, 0.f);
}

// ---------------------------------------------------------------------------
// Detect whether edge_index buffer is int64 or int32. For int64 (values
// in [0, N) << 2^31), the high word of every element is 0. For int32 random
// data the chance that 64 consecutive odd words are all zero is ~0.
__global__ void detect_kernel(const int* __restrict__ ei32) {
    int ok = 1;
#pragma unroll
    for (int k = 0; k < 64; k++)
        if (ei32[2 * k + 1] != 0) ok = 0;
    g_idx64 = ok;
}

// ---------------------------------------------------------------------------
// Edge scatter: one warp per edge. Each lane moves one float4 (16B) of the
// source row into agg[dst] via vectorized red.global.add.v4.f32.
__global__ void scatter_kernel(const void* __restrict__ ei_raw,
                               const float* __restrict__ x,
                               int E) {
    int warp = (blockIdx.x * blockDim.x + threadIdx.x) >> 5;
    int lane = threadIdx.x & 31;
    if (warp >= E) return;

    long long src, dst;
    if (g_idx64) {
        const long long* ei = (const long long*)ei_raw;
        src = ei[warp];
        dst = ei[E + warp];
    } else {
        const int* ei = (const int*)ei_raw;
        src = ei[warp];
        dst = ei[E + warp];
    }

    float4 val = reinterpret_cast<const float4*>(x + src * DD)[lane];
    float* p = g_agg + dst * DD + lane * 4;
    asm volatile("red.global.add.v4.f32 [%0], {%1,%2,%3,%4};"
                 :: "l"(p), "f"(val.x), "f"(val.y), "f"(val.z), "f"(val.w)
                 : "memory");
    if (lane == 0) atomicAdd(&g_deg[dst], 1.0f);
}

// ---------------------------------------------------------------------------
__global__ void invdeg_kernel(int N) {
    int i = blockIdx.x * blockDim.x + threadIdx.x;
    if (i < N) g_deg[i] = 1.0f / fmaxf(g_deg[i], 1.0f);
}

// ---------------------------------------------------------------------------
// Fused: h = (agg*invdeg) @ W_l^T + b_l + x @ W_r^T ; relu ; store h ;
// accumulate per-column sum / sum-of-squares for BN.
// C[N x 128] = A[N x 256] * B[256 x 128]:
//   A[:, 0:128]   = agg * invdeg,  B[k, j]     = W_l[j, k]
//   A[:, 128:256] = x,             B[128+k, j] = W_r[j, k]
// Tile: BM=128, full-width BN=128, BK=16; 256 threads; 8x8 per thread.
__global__ __launch_bounds__(256, 2)
void gemm_bn_kernel(const float* __restrict__ x,
                    const float* __restrict__ W_l,
                    const float* __restrict__ b_l,
                    const float* __restrict__ W_r,
                    float* __restrict__ out,
                    int N) {
    __shared__ float As[16][136];
    __shared__ float Bs[16][136];

    const int tid = threadIdx.x;
    const int tx = tid & 15;   // column group (8 cols)
    const int ty = tid >> 4;   // row group (8 rows)
    const int rowBase = blockIdx.x * 128;

    float c[8][8];
#pragma unroll
    for (int i = 0; i < 8; i++)
#pragma unroll
        for (int j = 0; j < 8; j++) c[i][j] = 0.f;

    const int lm = tid >> 1;        // 0..127 : row (A) or out-col j (B)
    const int lk = (tid & 1) * 8;   // 0 or 8 : k offset within tile

    for (int kt = 0; kt < 16; kt++) {
        const int kk = kt * 16;
        const bool isAgg = (kk < 128);
        const int kofs = isAgg ? kk : (kk - 128);

        // --- load A tile ---
        {
            int row = rowBase + lm;
            float4 f0 = make_float4(0, 0, 0, 0), f1 = f0;
            if (row < N) {
                const float* base = (isAgg ? g_agg : x) + (size_t)row * DD + kofs + lk;
                f0 = reinterpret_cast<const float4*>(base)[0];
                f1 = reinterpret_cast<const float4*>(base)[1];
                if (isAgg) {
                    float iv = g_deg[row];
                    f0.x *= iv; f0.y *= iv; f0.z *= iv; f0.w *= iv;
                    f1.x *= iv; f1.y *= iv; f1.z *= iv; f1.w *= iv;
                }
            }
            As[lk + 0][lm] = f0.x; As[lk + 1][lm] = f0.y;
            As[lk + 2][lm] = f0.z; As[lk + 3][lm] = f0.w;
            As[lk + 4][lm] = f1.x; As[lk + 5][lm] = f1.y;
            As[lk + 6][lm] = f1.z; As[lk + 7][lm] = f1.w;
        }
        // --- load B tile (transposed from W[j][k]) ---
        {
            const float* W = isAgg ? W_l : W_r;
            const float* base = W + (size_t)lm * DD + kofs + lk;
            float4 f0 = reinterpret_cast<const float4*>(base)[0];
            float4 f1 = reinterpret_cast<const float4*>(base)[1];
            Bs[lk + 0][lm] = f0.x; Bs[lk + 1][lm] = f0.y;
            Bs[lk + 2][lm] = f0.z; Bs[lk + 3][lm] = f0.w;
            Bs[lk + 4][lm] = f1.x; Bs[lk + 5][lm] = f1.y;
            Bs[lk + 6][lm] = f1.z; Bs[lk + 7][lm] = f1.w;
        }
        __syncthreads();

#pragma unroll
        for (int k = 0; k < 16; k++) {
            float a[8], b[8];
#pragma unroll
            for (int i = 0; i < 8; i++) a[i] = As[k][ty * 8 + i];
#pragma unroll
            for (int j = 0; j < 8; j++) b[j] = Bs[k][tx * 8 + j];
#pragma unroll
            for (int i = 0; i < 8; i++)
#pragma unroll
                for (int j = 0; j < 8; j++) c[i][j] = fmaf(a[i], b[j], c[i][j]);
        }
        __syncthreads();
    }

    // --- epilogue: +bias, relu, store, BN stats ---
    float bias[8];
#pragma unroll
    for (int j = 0; j < 8; j++) bias[j] = b_l[tx * 8 + j];

    float psum[8], psq[8];
#pragma unroll
    for (int j = 0; j < 8; j++) { psum[j] = 0.f; psq[j] = 0.f; }

#pragma unroll
    for (int i = 0; i < 8; i++) {
        int row = rowBase + ty * 8 + i;
        if (row < N) {
            float4 o0, o1;
            float v;
            v = fmaxf(c[i][0] + bias[0], 0.f); o0.x = v; psum[0] += v; psq[0] += v * v;
            v = fmaxf(c[i][1] + bias[1], 0.f); o0.y = v; psum[1] += v; psq[1] += v * v;
            v = fmaxf(c[i][2] + bias[2], 0.f); o0.z = v; psum[2] += v; psq[2] += v * v;
            v = fmaxf(c[i][3] + bias[3], 0.f); o0.w = v; psum[3] += v; psq[3] += v * v;
            v = fmaxf(c[i][4] + bias[4], 0.f); o1.x = v; psum[4] += v; psq[4] += v * v;
            v = fmaxf(c[i][5] + bias[5], 0.f); o1.y = v; psum[5] += v; psq[5] += v * v;
            v = fmaxf(c[i][6] + bias[6], 0.f); o1.z = v; psum[6] += v; psq[6] += v * v;
            v = fmaxf(c[i][7] + bias[7], 0.f); o1.w = v; psum[7] += v; psq[7] += v * v;
            float4* dst = reinterpret_cast<float4*>(out + (size_t)row * DD + tx * 8);
            dst[0] = o0; dst[1] = o1;
        }
    }

    // block reduce partial column stats (reuse As/Bs as scratch)
#pragma unroll
    for (int j = 0; j < 8; j++) {
        As[ty][tx * 8 + j] = psum[j];
        Bs[ty][tx * 8 + j] = psq[j];
    }
    __syncthreads();
    if (ty == 0) {
#pragma unroll
        for (int j = 0; j < 8; j++) {
            int col = tx * 8 + j;
            float s = 0.f;
#pragma unroll
            for (int r = 0; r < 16; r++) s += As[r][col];
            atomicAdd(&g_colsum[col], s);
        }
    } else if (ty == 1) {
#pragma unroll
        for (int j = 0; j < 8; j++) {
            int col = tx * 8 + j;
            float s = 0.f;
#pragma unroll
            for (int r = 0; r < 16; r++) s += Bs[r][col];
            atomicAdd(&g_colsumsq[col], s);
        }
    }
}

// ---------------------------------------------------------------------------
__global__ void bn_prep_kernel(const float* __restrict__ gamma,
                               const float* __restrict__ beta,
                               float invN) {
    int j = threadIdx.x;
    if (j < DD) {
        float mu = g_colsum[j] * invN;
        float var = fmaxf(g_colsumsq[j] * invN - mu * mu, 0.f);
        float rs = rsqrtf(var + BN_EPS);
        float sc = gamma[j] * rs;
        g_scale[j] = sc;
        g_shift[j] = beta[j] - mu * sc;
    }
}

__global__ void bn_apply_kernel(float* __restrict__ out, int n4) {
    int i = blockIdx.x * blockDim.x + threadIdx.x;
    if (i >= n4) return;
    int j = (i & 31) * 4;  // column of first element of this float4
    float4 v = reinterpret_cast<float4*>(out)[i];
    v.x = v.x * g_scale[j + 0] + g_shift[j + 0];
    v.y = v.y * g_scale[j + 1] + g_shift[j + 1];
    v.z = v.z * g_scale[j + 2] + g_shift[j + 2];
    v.w = v.w * g_scale[j + 3] + g_shift[j + 3];
    reinterpret_cast<float4*>(out)[i] = v;
}

// ---------------------------------------------------------------------------
extern "C" void kernel_launch(void* const* d_in, const int* in_sizes, int n_in,
                              void* d_out, int out_size) {
    const float* x     = (const float*)d_in[0];
    const void*  ei    = d_in[1];
    const float* W_l   = (const float*)d_in[2];
    const float* b_l   = (const float*)d_in[3];
    const float* W_r   = (const float*)d_in[4];
    const float* gamma = (const float*)d_in[5];
    const float* beta  = (const float*)d_in[6];
    float* out         = (float*)d_out;

    const int N = in_sizes[0] / DD;    // 100000
    const int E = in_sizes[1] / 2;     // 1600000

    float* agg_ptr; cudaGetSymbolAddress((void**)&agg_ptr, g_agg);
    float* deg_ptr; cudaGetSymbolAddress((void**)&deg_ptr, g_deg);
    float* cs_ptr;  cudaGetSymbolAddress((void**)&cs_ptr, g_colsum);
    float* csq_ptr; cudaGetSymbolAddress((void**)&csq_ptr, g_colsumsq);

    // 0. detect edge_index dtype (int32 vs int64)
    detect_kernel<<<1, 1>>>((const int*)ei);

    // 1-3. zero scratch
    {
        int n4 = N * (DD / 4);
        zero_kernel<<<(n4 + 255) / 256, 256>>>(agg_ptr, n4);
    }
    zero_kernel<<<(N / 4 + 255) / 256, 256>>>(deg_ptr, N / 4);
    zero_kernel<<<1, 64>>>(cs_ptr, DD / 4);
    zero_kernel<<<1, 64>>>(csq_ptr, DD / 4);

    // 4. edge scatter: one warp per edge, 8 warps per block
    scatter_kernel<<<(E + 7) / 8, 256>>>(ei, x, E);

    // 5. invdeg
    invdeg_kernel<<<(N + 255) / 256, 256>>>(N);

    // 6. fused GEMM + relu + BN stats
    gemm_bn_kernel<<<(N + 127) / 128, 256>>>(x, W_l, b_l, W_r, out, N);

    // 7. BN scale/shift
    bn_prep_kernel<<<1, 128>>>(gamma, beta, 1.0f / (float)N);

    // 8. BN apply in place
    {
        int n4 = N * (DD / 4);
        bn_apply_kernel<<<(n4 + 255) / 256, 256>>>(out, n4);
    }
}

// round 3
// speedup vs baseline: 1.3425x; 1.3425x over previous
#include <cuda_runtime.h>
#include <cuda_bf16.h>
#include <cstdint>

// Problem constants: N=100000 nodes, D=128, E=1600000 edges.
#define MAX_N 100000
#define MAX_E 2000000
#define DD 128
#define BN_EPS 1e-5f

// Scratch (static __device__ — no allocations allowed)
__device__ __align__(16) float g_agg[MAX_N * DD];     // mean-aggregated features
__device__ int   g_degi[MAX_N];                        // int degree
__device__ int   g_rowstart[MAX_N + 1];                // CSR row offsets
__device__ int   g_cursor[MAX_N];                      // fill cursors
__device__ int   g_csr[MAX_E];                         // src ids grouped by dst
__device__ int   g_bsum[256];                          // scan block sums
__device__ int   g_boff[256];                          // scan block offsets
__device__ __align__(16) float g_colsum[DD];
__device__ __align__(16) float g_colsumsq[DD];
__device__ __align__(16) float g_scale[DD];
__device__ __align__(16) float g_shift[DD];
__device__ int g_idx64;                                // 1 if edge_index is int64

// ---------------------------------------------------------------------------
// 1. zero degree hist + detect edge_index dtype (int64 high words all zero)
__global__ void init_kernel(const int* __restrict__ ei32, int N) {
    int i = blockIdx.x * blockDim.x + threadIdx.x;
    if (i < N) g_degi[i] = 0;
    if (i == 0) {
        int ok = 1;
#pragma unroll
        for (int k = 0; k < 64; k++) ok &= (ei32[2 * k + 1] == 0);
        g_idx64 = ok;
    }
}

// ---------------------------------------------------------------------------
// 2. degree histogram over dst
__global__ void hist_kernel(const void* __restrict__ ei_raw, int E) {
    int e = blockIdx.x * blockDim.x + threadIdx.x;
    if (e >= E) return;
    int dst;
    if (g_idx64) dst = (int)((const long long*)ei_raw)[E + e];
    else         dst = ((const int*)ei_raw)[E + e];
    atomicAdd(&g_degi[dst], 1);
}

// ---------------------------------------------------------------------------
// 3. scan pass 1: per-block (1024 elements) exclusive scan + block totals
__global__ void scan_p1_kernel(int N) {
    __shared__ int wsum[8];
    const int t = threadIdx.x;
    const int lane = t & 31, w = t >> 5;
    const int base = blockIdx.x * 1024 + t * 4;

    int v0 = 0, v1 = 0, v2 = 0, v3 = 0;
    if (base + 0 < N) v0 = g_degi[base + 0];
    if (base + 1 < N) v1 = g_degi[base + 1];
    if (base + 2 < N) v2 = g_degi[base + 2];
    if (base + 3 < N) v3 = g_degi[base + 3];
    const int s = v0 + v1 + v2 + v3;

    int incl = s;
#pragma unroll
    for (int o = 1; o < 32; o <<= 1) {
        int n = __shfl_up_sync(0xFFFFFFFFu, incl, o);
        if (lane >= o) incl += n;
    }
    if (lane == 31) wsum[w] = incl;
    __syncthreads();
    if (w == 0) {
        int ws = (lane < 8) ? wsum[lane] : 0;
#pragma unroll
        for (int o = 1; o < 8; o <<= 1) {
            int n = __shfl_up_sync(0xFFFFFFFFu, ws, o);
            if (lane >= o) ws += n;
        }
        if (lane < 8) wsum[lane] = ws;  // inclusive warp sums
    }
    __syncthreads();
    const int woff = (w > 0) ? wsum[w - 1] : 0;
    const int te = woff + incl - s;     // thread exclusive prefix
    if (base + 0 < N) g_rowstart[base + 0] = te;
    if (base + 1 < N) g_rowstart[base + 1] = te + v0;
    if (base + 2 < N) g_rowstart[base + 2] = te + v0 + v1;
    if (base + 3 < N) g_rowstart[base + 3] = te + v0 + v1 + v2;
    if (t == 255) g_bsum[blockIdx.x] = woff + incl;  // block total
}

// 4. scan pass 2: exclusive scan of block totals (nb <= 128); zero BN stats
__global__ void scan_p2_kernel(int nb) {
    __shared__ int ws2[4];
    const int t = threadIdx.x;        // 128 threads
    const int lane = t & 31, w = t >> 5;
    int v = (t < nb) ? g_bsum[t] : 0;
    int incl = v;
#pragma unroll
    for (int o = 1; o < 32; o <<= 1) {
        int n = __shfl_up_sync(0xFFFFFFFFu, incl, o);
        if (lane >= o) incl += n;
    }
    if (lane == 31) ws2[w] = incl;
    __syncthreads();
    if (w == 0 && lane < 4) {
        int x = ws2[lane];
#pragma unroll
        for (int o = 1; o < 4; o <<= 1) {
            int n = __shfl_up_sync(0x0000000Fu, x, o);
            if (lane >= o) x += n;
        }
        ws2[lane] = x;
    }
    __syncthreads();
    incl += (w > 0) ? ws2[w - 1] : 0;
    g_boff[t] = incl - v;   // exclusive
    // zero BN stat accumulators (block has 128 threads == DD)
    g_colsum[t] = 0.f;
    g_colsumsq[t] = 0.f;
}

// 5. scan pass 3: add block offsets; produce rowstart + cursor copy
__global__ void scan_p3_kernel(int N, int E) {
    int i = blockIdx.x * blockDim.x + threadIdx.x;
    if (i < N) {
        int r = g_rowstart[i] + g_boff[i >> 10];
        g_rowstart[i] = r;
        g_cursor[i] = r;
    }
    if (i == 0) g_rowstart[N] = E;
}

// ---------------------------------------------------------------------------
// 6. CSR fill: group src ids by dst
__global__ void fill_kernel(const void* __restrict__ ei_raw, int E) {
    int e = blockIdx.x * blockDim.x + threadIdx.x;
    if (e >= E) return;
    int src, dst;
    if (g_idx64) {
        const long long* p = (const long long*)ei_raw;
        src = (int)p[e]; dst = (int)p[E + e];
    } else {
        const int* p = (const int*)ei_raw;
        src = p[e]; dst = p[E + e];
    }
    int pos = atomicAdd(&g_cursor[dst], 1);
    g_csr[pos] = src;
}

// ---------------------------------------------------------------------------
// 7. Gather-aggregate: one warp per node; each lane owns one float4 of the
// row; accumulate neighbor rows in registers; write mean with plain stores.
__global__ __launch_bounds__(256)
void gather_kernel(const float* __restrict__ x, int N) {
    const int warp = (blockIdx.x * blockDim.x + threadIdx.x) >> 5;
    const int lane = threadIdx.x & 31;
    if (warp >= N) return;

    const int start = g_rowstart[warp];
    const int end   = g_rowstart[warp + 1];

    float4 acc = make_float4(0.f, 0.f, 0.f, 0.f);
    for (int eb = start; eb < end; eb += 32) {
        int n = end - eb; if (n > 32) n = 32;
        int myid = (lane < n) ? g_csr[eb + lane] : 0;
        for (int j = 0; j < n; j++) {
            int s = __shfl_sync(0xFFFFFFFFu, myid, j);
            float4 v = reinterpret_cast<const float4*>(x + (size_t)s * DD)[lane];
            acc.x += v.x; acc.y += v.y; acc.z += v.z; acc.w += v.w;
        }
    }
    const float inv = 1.0f / fmaxf((float)(end - start), 1.0f);
    float4 o = make_float4(acc.x * inv, acc.y * inv, acc.z * inv, acc.w * inv);
    reinterpret_cast<float4*>(g_agg + (size_t)warp * DD)[lane] = o;
}

// ---------------------------------------------------------------------------
// 8. Fused: h = mean @ W_l^T + b_l + x @ W_r^T ; relu ; store h ; BN stats.
// C[N x 128] = A[N x 256] * B[256 x 128]:
//   A[:, 0:128] = g_agg (mean),  B[k, j] = W_l[j, k]
//   A[:, 128:256] = x,           B[128+k, j] = W_r[j, k]
__global__ __launch_bounds__(256, 2)
void gemm_bn_kernel(const float* __restrict__ x,
                    const float* __restrict__ W_l,
                    const float* __restrict__ b_l,
                    const float* __restrict__ W_r,
                    float* __restrict__ out,
                    int N) {
    __shared__ float As[16][136];
    __shared__ float Bs[16][136];

    const int tid = threadIdx.x;
    const int tx = tid & 15;
    const int ty = tid >> 4;
    const int rowBase = blockIdx.x * 128;

    float c[8][8];
#pragma unroll
    for (int i = 0; i < 8; i++)
#pragma unroll
        for (int j = 0; j < 8; j++) c[i][j] = 0.f;

    const int lm = tid >> 1;
    const int lk = (tid & 1) * 8;

    for (int kt = 0; kt < 16; kt++) {
        const int kk = kt * 16;
        const bool isAgg = (kk < 128);
        const int kofs = isAgg ? kk : (kk - 128);

        {
            int row = rowBase + lm;
            float4 f0 = make_float4(0, 0, 0, 0), f1 = f0;
            if (row < N) {
                const float* base = (isAgg ? g_agg : x) + (size_t)row * DD + kofs + lk;
                f0 = reinterpret_cast<const float4*>(base)[0];
                f1 = reinterpret_cast<const float4*>(base)[1];
            }
            As[lk + 0][lm] = f0.x; As[lk + 1][lm] = f0.y;
            As[lk + 2][lm] = f0.z; As[lk + 3][lm] = f0.w;
            As[lk + 4][lm] = f1.x; As[lk + 5][lm] = f1.y;
            As[lk + 6][lm] = f1.z; As[lk + 7][lm] = f1.w;
        }
        {
            const float* W = isAgg ? W_l : W_r;
            const float* base = W + (size_t)lm * DD + kofs + lk;
            float4 f0 = reinterpret_cast<const float4*>(base)[0];
            float4 f1 = reinterpret_cast<const float4*>(base)[1];
            Bs[lk + 0][lm] = f0.x; Bs[lk + 1][lm] = f0.y;
            Bs[lk + 2][lm] = f0.z; Bs[lk + 3][lm] = f0.w;
            Bs[lk + 4][lm] = f1.x; Bs[lk + 5][lm] = f1.y;
            Bs[lk + 6][lm] = f1.z; Bs[lk + 7][lm] = f1.w;
        }
        __syncthreads();

#pragma unroll
        for (int k = 0; k < 16; k++) {
            float a[8], b[8];
#pragma unroll
            for (int i = 0; i < 8; i++) a[i] = As[k][ty * 8 + i];
#pragma unroll
            for (int j = 0; j < 8; j++) b[j] = Bs[k][tx * 8 + j];
#pragma unroll
            for (int i = 0; i < 8; i++)
#pragma unroll
                for (int j = 0; j < 8; j++) c[i][j] = fmaf(a[i], b[j], c[i][j]);
        }
        __syncthreads();
    }

    float bias[8];
#pragma unroll
    for (int j = 0; j < 8; j++) bias[j] = b_l[tx * 8 + j];

    float psum[8], psq[8];
#pragma unroll
    for (int j = 0; j < 8; j++) { psum[j] = 0.f; psq[j] = 0.f; }

#pragma unroll
    for (int i = 0; i < 8; i++) {
        int row = rowBase + ty * 8 + i;
        if (row < N) {
            float4 o0, o1;
            float v;
            v = fmaxf(c[i][0] + bias[0], 0.f); o0.x = v; psum[0] += v; psq[0] += v * v;
            v = fmaxf(c[i][1] + bias[1], 0.f); o0.y = v; psum[1] += v; psq[1] += v * v;
            v = fmaxf(c[i][2] + bias[2], 0.f); o0.z = v; psum[2] += v; psq[2] += v * v;
            v = fmaxf(c[i][3] + bias[3], 0.f); o0.w = v; psum[3] += v; psq[3] += v * v;
            v = fmaxf(c[i][4] + bias[4], 0.f); o1.x = v; psum[4] += v; psq[4] += v * v;
            v = fmaxf(c[i][5] + bias[5], 0.f); o1.y = v; psum[5] += v; psq[5] += v * v;
            v = fmaxf(c[i][6] + bias[6], 0.f); o1.z = v; psum[6] += v; psq[6] += v * v;
            v = fmaxf(c[i][7] + bias[7], 0.f); o1.w = v; psum[7] += v; psq[7] += v * v;
            float4* dst = reinterpret_cast<float4*>(out + (size_t)row * DD + tx * 8);
            dst[0] = o0; dst[1] = o1;
        }
    }

#pragma unroll
    for (int j = 0; j < 8; j++) {
        As[ty][tx * 8 + j] = psum[j];
        Bs[ty][tx * 8 + j] = psq[j];
    }
    __syncthreads();
    if (ty == 0) {
#pragma unroll
        for (int j = 0; j < 8; j++) {
            int col = tx * 8 + j;
            float s = 0.f;
#pragma unroll
            for (int r = 0; r < 16; r++) s += As[r][col];
            atomicAdd(&g_colsum[col], s);
        }
    } else if (ty == 1) {
#pragma unroll
        for (int j = 0; j < 8; j++) {
            int col = tx * 8 + j;
            float s = 0.f;
#pragma unroll
            for (int r = 0; r < 16; r++) s += Bs[r][col];
            atomicAdd(&g_colsumsq[col], s);
        }
    }
}

// ---------------------------------------------------------------------------
__global__ void bn_prep_kernel(const float* __restrict__ gamma,
                               const float* __restrict__ beta,
                               float invN) {
    int j = threadIdx.x;
    if (j < DD) {
        float mu = g_colsum[j] * invN;
        float var = fmaxf(g_colsumsq[j] * invN - mu * mu, 0.f);
        float rs = rsqrtf(var + BN_EPS);
        float sc = gamma[j] * rs;
        g_scale[j] = sc;
        g_shift[j] = beta[j] - mu * sc;
    }
}

__global__ void bn_apply_kernel(float* __restrict__ out, int n4) {
    int i = blockIdx.x * blockDim.x + threadIdx.x;
    if (i >= n4) return;
    int j = (i & 31) * 4;
    float4 v = reinterpret_cast<float4*>(out)[i];
    v.x = v.x * g_scale[j + 0] + g_shift[j + 0];
    v.y = v.y * g_scale[j + 1] + g_shift[j + 1];
    v.z = v.z * g_scale[j + 2] + g_shift[j + 2];
    v.w = v.w * g_scale[j + 3] + g_shift[j + 3];
    reinterpret_cast<float4*>(out)[i] = v;
}

// ---------------------------------------------------------------------------
extern "C" void kernel_launch(void* const* d_in, const int* in_sizes, int n_in,
                              void* d_out, int out_size) {
    const float* x     = (const float*)d_in[0];
    const void*  ei    = d_in[1];
    const float* W_l   = (const float*)d_in[2];
    const float* b_l   = (const float*)d_in[3];
    const float* W_r   = (const float*)d_in[4];
    const float* gamma = (const float*)d_in[5];
    const float* beta  = (const float*)d_in[6];
    float* out         = (float*)d_out;

    const int N = in_sizes[0] / DD;    // 100000
    const int E = in_sizes[1] / 2;     // 1600000
    const int nScanBlocks = (N + 1023) / 1024;   // 98

    // 1. zero degree hist + dtype detect
    init_kernel<<<(N + 255) / 256, 256>>>((const int*)ei, N);
    // 2. degree histogram
    hist_kernel<<<(E + 255) / 256, 256>>>(ei, E);
    // 3-5. exclusive scan -> rowstart, cursor; zero BN stats
    scan_p1_kernel<<<nScanBlocks, 256>>>(N);
    scan_p2_kernel<<<1, 128>>>(nScanBlocks);
    scan_p3_kernel<<<(N + 255) / 256, 256>>>(N, E);
    // 6. CSR fill
    fill_kernel<<<(E + 255) / 256, 256>>>(ei, E);
    // 7. gather-aggregate (one warp per node)
    gather_kernel<<<(N + 7) / 8, 256>>>(x, N);
    // 8. fused GEMM + relu + BN stats
    gemm_bn_kernel<<<(N + 127) / 128, 256>>>(x, W_l, b_l, W_r, out, N);
    // 9. BN scale/shift
    bn_prep_kernel<<<1, 128>>>(gamma, beta, 1.0f / (float)N);
    // 10. BN apply in place
    bn_apply_kernel<<<(N * (DD / 4) + 255) / 256, 256>>>(out, N * (DD / 4));
}